// round 1
// baseline (speedup 1.0000x reference)
#include <cuda_runtime.h>

// Reverse cummax along axis 1 of [B=16, H=128, W=128, C=256] fp32.
// out[b,h,w,c] = max_{h'>=h} in[b,h',w,c]
//
// One thread per (b, w, c4) column of float4. Walks h from H-1 down to 0
// with a register-resident running max. Fully coalesced: adjacent threads
// own adjacent 16B chunks. Pure streaming: 256MB read + 256MB write.

static constexpr int B = 16;
static constexpr int H = 128;
static constexpr int W = 128;
static constexpr int C = 256;
static constexpr int C4 = C / 4;                 // 64 float4 per (w) row
static constexpr int PLANE4 = W * C4;            // float4 per (b,h) slice = 8192
static constexpr int HSTRIDE4 = PLANE4;          // float4 stride along h
static constexpr long long NCOL = (long long)B * W * C4;  // 131072 columns

__global__ __launch_bounds__(256) void suffix_cummax_kernel(
    const float4* __restrict__ in, float4* __restrict__ out)
{
    int col = blockIdx.x * blockDim.x + threadIdx.x;  // 0 .. NCOL-1
    if (col >= NCOL) return;

    // col -> (b, w, c4): c4 fastest, then w, then b
    int c4 = col & (C4 - 1);
    int w  = (col >> 6) & (W - 1);       // C4 = 64 = 2^6
    int b  = col >> 13;                  // W*C4 = 8192 = 2^13

    // base index (in float4 units) of (b, h=0, w, c4)
    long long base = (long long)b * H * PLANE4 + (long long)w * C4 + c4;

    const float4* ip = in  + base + (long long)(H - 1) * HSTRIDE4;
    float4*       op = out + base + (long long)(H - 1) * HSTRIDE4;

    float4 run;
    run.x = -__int_as_float(0x7f800000);  // -inf
    run.y = run.x; run.z = run.x; run.w = run.x;

    // h = H-1 down to 0, unrolled x4 for MLP (loads are address-independent)
    #pragma unroll 4
    for (int h = H - 1; h >= 0; --h) {
        float4 v = *ip;
        run.x = fmaxf(run.x, v.x);
        run.y = fmaxf(run.y, v.y);
        run.z = fmaxf(run.z, v.z);
        run.w = fmaxf(run.w, v.w);
        *op = run;
        ip -= HSTRIDE4;
        op -= HSTRIDE4;
    }
}

extern "C" void kernel_launch(void* const* d_in, const int* in_sizes, int n_in,
                              void* d_out, int out_size)
{
    const float4* in  = (const float4*)d_in[0];
    float4*       out = (float4*)d_out;

    int threads = 256;
    int blocks = (int)((NCOL + threads - 1) / threads);  // 512
    suffix_cummax_kernel<<<blocks, threads>>>(in, out);
}